// round 1
// baseline (speedup 1.0000x reference)
#include <cuda_runtime.h>
#include <math.h>

#define Bsz  32
#define Tlen 512
#define Idim 1024
#define Hdim 1024
#define G4   4096   // 4*H

// ---------------- device scratch (static globals: allocation-free at runtime) ----
__device__ float g_xw[(size_t)Tlen * Bsz * G4];   // [t][b][4H] precomputed input proj (+bias)
__device__ float g_hT[2][Hdim * Bsz];             // double-buffered h, transposed [h][b]
__device__ unsigned int g_bar;                    // grid barrier counter

__global__ void reset_kernel() { g_bar = 0u; }

// =======================================================================
// Phase 1: xW[t][b][n] = sum_k x[b*T+t][k] * Wih[n][k] + bias[n]
// Classic SGEMM NT: BM=64, BN=64, BK=16, 256 threads, 4x4 microtile.
// =======================================================================
#define BM 64
#define BN 64
#define BK 16

__global__ __launch_bounds__(256) void gemm_xw_kernel(
    const float* __restrict__ x, const float* __restrict__ Wih,
    const float* __restrict__ bias)
{
    __shared__ float As[BK][BM];
    __shared__ float Bs[BK][BN];

    const int tid = threadIdx.x;
    const int bn  = blockIdx.x * BN;
    const int bm  = blockIdx.y * BM;
    const int tx  = tid & 15;        // 16 col-groups
    const int ty  = tid >> 4;        // 16 row-groups
    const int lrow = tid >> 2;       // 0..63 (tile row for loads)
    const int lkc  = (tid & 3) << 2; // 0,4,8,12 (k within BK)

    const float* xrow = x   + (size_t)(bm + lrow) * Idim + lkc;
    const float* wrow = Wih + (size_t)(bn + lrow) * Idim + lkc;

    float acc[4][4];
#pragma unroll
    for (int i = 0; i < 4; i++)
#pragma unroll
        for (int j = 0; j < 4; j++) acc[i][j] = 0.f;

    for (int k0 = 0; k0 < Idim; k0 += BK) {
        float4 av = *(const float4*)(xrow + k0);
        float4 bv = *(const float4*)(wrow + k0);
        __syncthreads();
        As[lkc + 0][lrow] = av.x; As[lkc + 1][lrow] = av.y;
        As[lkc + 2][lrow] = av.z; As[lkc + 3][lrow] = av.w;
        Bs[lkc + 0][lrow] = bv.x; Bs[lkc + 1][lrow] = bv.y;
        Bs[lkc + 2][lrow] = bv.z; Bs[lkc + 3][lrow] = bv.w;
        __syncthreads();
#pragma unroll
        for (int k = 0; k < BK; k++) {
            float4 a4 = *(const float4*)&As[k][ty << 2];
            float4 b4 = *(const float4*)&Bs[k][tx << 2];
            float ar[4] = {a4.x, a4.y, a4.z, a4.w};
            float br[4] = {b4.x, b4.y, b4.z, b4.w};
#pragma unroll
            for (int i = 0; i < 4; i++)
#pragma unroll
                for (int j = 0; j < 4; j++)
                    acc[i][j] = fmaf(ar[i], br[j], acc[i][j]);
        }
    }

    float4 bb = *(const float4*)&bias[bn + (tx << 2)];
#pragma unroll
    for (int i = 0; i < 4; i++) {
        int m = bm + (ty << 2) + i;
        int t = m & (Tlen - 1);
        int b = m >> 9;             // m / Tlen
        float4 o;
        o.x = acc[i][0] + bb.x; o.y = acc[i][1] + bb.y;
        o.z = acc[i][2] + bb.z; o.w = acc[i][3] + bb.w;
        *(float4*)&g_xw[(size_t)t * (Bsz * G4) + (size_t)b * G4 + bn + (tx << 2)] = o;
    }
}

// =======================================================================
// Phase 2: persistent recurrent kernel. 128 blocks x 256 threads.
// Block bid owns h-columns [bid*8, bid*8+8); warp wi owns h-column hc=bid*8+wi,
// lane = batch. c-state is register resident. W_hh slice (32 rows x 1024) in SMEM.
// =======================================================================
#define NBLK 128
#define SH_W_FLOATS (32 * 1024)          // 128 KB
#define SH_H_FLOATS (2 * 128 * 32)       // 32 KB (double-buffered 128-k chunk)
#define SMEM_BYTES ((SH_W_FLOATS + SH_H_FLOATS) * 4)

__device__ __forceinline__ void grid_barrier(unsigned target)
{
    __threadfence();
    __syncthreads();
    if (threadIdx.x == 0) {
        atomicAdd(&g_bar, 1u);
        while (atomicAdd(&g_bar, 0u) < target) { }
    }
    __syncthreads();
}

__device__ __forceinline__ float sigmoidf_(float v) { return 1.f / (1.f + expf(-v)); }

__global__ void __launch_bounds__(256, 1) lstm_rec_kernel(
    const float* __restrict__ Whh, float* __restrict__ out)
{
    extern __shared__ float smem[];
    float* sw = smem;                    // [32][1024], row r = gate*8 + warp
    float* sh = smem + SH_W_FLOATS;      // [2][128][32]

    const int tid  = threadIdx.x;
    const int bid  = blockIdx.x;         // 0..127
    const int wi   = tid >> 5;           // 0..7 -> local h-column
    const int lane = tid & 31;           // batch index
    const int hc   = (bid << 3) + wi;    // global h column

    // ---- load this block's 32 W_hh rows (4 gates x 8 h-cols) into SMEM once ----
    for (int idx = tid; idx < 32 * 256; idx += 256) {
        int r  = idx >> 8;               // local row 0..31
        int c4 = (idx & 255) << 2;       // k offset
        int g  = r >> 3, wl = r & 7;
        float4 v = *(const float4*)(Whh + (size_t)(g * Hdim + (bid << 3) + wl) * Hdim + c4);
        *(float4*)(sw + r * 1024 + c4) = v;
    }

    // ---- init h buffer 0 = 0 (each warp zeroes its own row) ----
    g_hT[0][hc * Bsz + lane] = 0.f;

    float c_state = 0.f;
    unsigned target = NBLK;
    grid_barrier(target);                // all h zeros + W loaded visible

    const float* w0p = sw + (0 * 8 + wi) * 1024;
    const float* w1p = sw + (1 * 8 + wi) * 1024;
    const float* w2p = sw + (2 * 8 + wi) * 1024;
    const float* w3p = sw + (3 * 8 + wi) * 1024;

    for (int t = 0; t < Tlen; t++) {
        const float* hTr = g_hT[t & 1];
        float*       hTw = g_hT[(t + 1) & 1];

        // input projection for this (batch, h-col): 4 gates (DRAM, hidden by compute)
        const float* xwp = g_xw + (size_t)t * (Bsz * G4) + (size_t)lane * G4 + hc;
        float a0 = xwp[0];
        float a1 = xwp[1024];
        float a2 = xwp[2048];
        float a3 = xwp[3072];

        // ---- stage chunk 0 of h (128 k x 32 b = 16KB) via L2 (__ldcg: L1 not coherent) ----
        {
            const float* src = hTr + tid * 4;
            float4 r0 = __ldcg((const float4*)(src + 0));
            float4 r1 = __ldcg((const float4*)(src + 1024));
            float4 r2 = __ldcg((const float4*)(src + 2048));
            float4 r3 = __ldcg((const float4*)(src + 3072));
            float* dst = sh + tid * 4;
            *(float4*)(dst + 0)    = r0;
            *(float4*)(dst + 1024) = r1;
            *(float4*)(dst + 2048) = r2;
            *(float4*)(dst + 3072) = r3;
        }
        __syncthreads();

        for (int ch = 0; ch < 8; ch++) {
            const int p = ch & 1;
            float4 n0, n1, n2, n3;
            if (ch < 7) {   // prefetch next chunk while computing this one
                const float* src = hTr + (ch + 1) * 4096 + tid * 4;
                n0 = __ldcg((const float4*)(src + 0));
                n1 = __ldcg((const float4*)(src + 1024));
                n2 = __ldcg((const float4*)(src + 2048));
                n3 = __ldcg((const float4*)(src + 3072));
            }
            const float* shp = sh + p * 4096;
            const int kb = ch * 128;
#pragma unroll 8
            for (int k4 = 0; k4 < 32; k4++) {
                float4 w0 = *(const float4*)(w0p + kb + k4 * 4);
                float4 w1 = *(const float4*)(w1p + kb + k4 * 4);
                float4 w2 = *(const float4*)(w2p + kb + k4 * 4);
                float4 w3 = *(const float4*)(w3p + kb + k4 * 4);
                float h0 = shp[(k4 * 4 + 0) * 32 + lane];
                float h1 = shp[(k4 * 4 + 1) * 32 + lane];
                float h2 = shp[(k4 * 4 + 2) * 32 + lane];
                float h3 = shp[(k4 * 4 + 3) * 32 + lane];
                a0 = fmaf(w0.x, h0, a0); a0 = fmaf(w0.y, h1, a0);
                a0 = fmaf(w0.z, h2, a0); a0 = fmaf(w0.w, h3, a0);
                a1 = fmaf(w1.x, h0, a1); a1 = fmaf(w1.y, h1, a1);
                a1 = fmaf(w1.z, h2, a1); a1 = fmaf(w1.w, h3, a1);
                a2 = fmaf(w2.x, h0, a2); a2 = fmaf(w2.y, h1, a2);
                a2 = fmaf(w2.z, h2, a2); a2 = fmaf(w2.w, h3, a2);
                a3 = fmaf(w3.x, h0, a3); a3 = fmaf(w3.y, h1, a3);
                a3 = fmaf(w3.z, h2, a3); a3 = fmaf(w3.w, h3, a3);
            }
            if (ch < 7) {
                float* dst = sh + (1 - p) * 4096 + tid * 4;
                *(float4*)(dst + 0)    = n0;
                *(float4*)(dst + 1024) = n1;
                *(float4*)(dst + 2048) = n2;
                *(float4*)(dst + 3072) = n3;
                __syncthreads();
            }
        }

        // ---- gates (i, f, g, o) + state update ----
        float ig = sigmoidf_(a0);
        float fg = sigmoidf_(a1);
        float gg = tanhf(a2);
        float og = sigmoidf_(a3);
        c_state = fmaf(fg, c_state, ig * gg);
        float hv = og * tanhf(c_state);

        hTw[hc * Bsz + lane] = hv;                                    // coalesced
        out[(size_t)lane * (Tlen * Hdim) + (size_t)t * Hdim + hc] = hv;

        target += NBLK;
        grid_barrier(target);
    }
}

// =======================================================================
extern "C" void kernel_launch(void* const* d_in, const int* in_sizes, int n_in,
                              void* d_out, int out_size)
{
    const float* x    = (const float*)d_in[0];
    const float* Wih  = (const float*)d_in[1];
    const float* Whh  = (const float*)d_in[2];
    const float* bias = (const float*)d_in[3];
    float* out = (float*)d_out;

    cudaFuncSetAttribute(lstm_rec_kernel,
                         cudaFuncAttributeMaxDynamicSharedMemorySize, SMEM_BYTES);

    reset_kernel<<<1, 1>>>();

    dim3 g1(G4 / BN, (Bsz * Tlen) / BM);   // (64, 256)
    gemm_xw_kernel<<<g1, 256>>>(x, Wih, bias);

    lstm_rec_kernel<<<NBLK, 256, SMEM_BYTES>>>(Whh, out);
}

// round 2
// speedup vs baseline: 1.0805x; 1.0805x over previous
#include <cuda_runtime.h>
#include <math.h>

#define Bsz  32
#define Tlen 512
#define Idim 1024
#define Hdim 1024
#define G4   4096   // 4*H

// ---------------- device scratch ----------------
__device__ float g_xw[(size_t)Tlen * Bsz * G4];   // [t][b][4H]
__device__ float g_h2[2][Hdim * Bsz];             // pair-interleaved: [k2][b][2]
__device__ unsigned int g_bar;

// ---------------- f32x2 helpers ----------------
__device__ __forceinline__ void fma2(unsigned long long& acc,
                                     unsigned long long a, unsigned long long b)
{
    asm volatile("fma.rn.f32x2 %0, %1, %2, %0;" : "+l"(acc) : "l"(a), "l"(b));
}
__device__ __forceinline__ unsigned long long pack2(float lo, float hi)
{
    unsigned long long r;
    asm("mov.b64 %0, {%1, %2};" : "=l"(r) : "f"(lo), "f"(hi));
    return r;
}
__device__ __forceinline__ unsigned long long bcast2(float v)
{
    unsigned long long r;
    asm("mov.b64 %0, {%1, %1};" : "=l"(r) : "f"(v));
    return r;
}
__device__ __forceinline__ void unpack2(unsigned long long p, float& lo, float& hi)
{
    asm("mov.b64 {%0, %1}, %2;" : "=f"(lo), "=f"(hi) : "l"(p));
}
__device__ __forceinline__ void lds_v2u64(unsigned addr,
                                          unsigned long long& a, unsigned long long& b)
{
    asm volatile("ld.shared.v2.u64 {%0, %1}, [%2];" : "=l"(a), "=l"(b) : "r"(addr));
}
__device__ __forceinline__ unsigned long long lds_u64(unsigned addr)
{
    unsigned long long r;
    asm volatile("ld.shared.b64 %0, [%1];" : "=l"(r) : "r"(addr));
    return r;
}

// =======================================================================
// Phase 1: xW[t][b][n] = sum_k x[(b,t)][k] * Wih[n][k] + bias[n]
// BM=64, BN=64, BK=16, 256 threads, 4x4 microtile, f32x2 inner product.
// =======================================================================
#define BM 64
#define BN 64
#define BK 16

__global__ __launch_bounds__(256) void gemm_xw_kernel(
    const float* __restrict__ x, const float* __restrict__ Wih,
    const float* __restrict__ bias)
{
    __shared__ float As[BK][BM];
    __shared__ float Bs[BK][BN];

    // fold barrier reset into this kernel (runs before lstm in stream order)
    if (blockIdx.x == 0 && blockIdx.y == 0 && threadIdx.x == 0) g_bar = 0u;

    const int tid = threadIdx.x;
    const int bn  = blockIdx.x * BN;
    const int bm  = blockIdx.y * BM;
    const int tx  = tid & 15;
    const int ty  = tid >> 4;
    const int lrow = tid >> 2;
    const int lkc  = (tid & 3) << 2;

    const float* xrow = x   + (size_t)(bm + lrow) * Idim + lkc;
    const float* wrow = Wih + (size_t)(bn + lrow) * Idim + lkc;

    const unsigned bs_base =
        (unsigned)__cvta_generic_to_shared(&Bs[0][0]) + (unsigned)(tx << 4);

    unsigned long long acc[4][2];
#pragma unroll
    for (int i = 0; i < 4; i++) { acc[i][0] = 0ull; acc[i][1] = 0ull; }

    for (int k0 = 0; k0 < Idim; k0 += BK) {
        float4 av = *(const float4*)(xrow + k0);
        float4 bv = *(const float4*)(wrow + k0);
        __syncthreads();
        As[lkc + 0][lrow] = av.x; As[lkc + 1][lrow] = av.y;
        As[lkc + 2][lrow] = av.z; As[lkc + 3][lrow] = av.w;
        Bs[lkc + 0][lrow] = bv.x; Bs[lkc + 1][lrow] = bv.y;
        Bs[lkc + 2][lrow] = bv.z; Bs[lkc + 3][lrow] = bv.w;
        __syncthreads();
#pragma unroll
        for (int k = 0; k < BK; k++) {
            float4 a4 = *(const float4*)&As[k][ty << 2];
            unsigned long long b01, b23;
            lds_v2u64(bs_base + (unsigned)(k * (BN * 4)), b01, b23);
            unsigned long long aa;
            aa = bcast2(a4.x); fma2(acc[0][0], aa, b01); fma2(acc[0][1], aa, b23);
            aa = bcast2(a4.y); fma2(acc[1][0], aa, b01); fma2(acc[1][1], aa, b23);
            aa = bcast2(a4.z); fma2(acc[2][0], aa, b01); fma2(acc[2][1], aa, b23);
            aa = bcast2(a4.w); fma2(acc[3][0], aa, b01); fma2(acc[3][1], aa, b23);
        }
    }

    float4 bb = *(const float4*)&bias[bn + (tx << 2)];
#pragma unroll
    for (int i = 0; i < 4; i++) {
        int m = bm + (ty << 2) + i;
        int t = m & (Tlen - 1);
        int b = m >> 9;
        float4 o;
        unpack2(acc[i][0], o.x, o.y);
        unpack2(acc[i][1], o.z, o.w);
        o.x += bb.x; o.y += bb.y; o.z += bb.z; o.w += bb.w;
        *(float4*)&g_xw[(size_t)t * (Bsz * G4) + (size_t)b * G4 + bn + (tx << 2)] = o;
    }
}

// =======================================================================
// Phase 2: persistent recurrent kernel (128 blocks x 256 threads).
// Warp wi of block bid owns h-column hc = bid*8+wi; lane = batch.
// c-state register resident; W_hh slice (32 rows x 1024) in SMEM.
// h exchanged via global in pair-interleaved [k2][b][2] layout -> LDS.64
// yields ready-packed f32x2 operands.
// =======================================================================
#define NBLK 128
#define SH_W_FLOATS (32 * 1024)          // 128 KB
#define SH_H_FLOATS (2 * 128 * 32)       // 32 KB (double-buffered 128-k chunk)
#define SMEM_BYTES ((SH_W_FLOATS + SH_H_FLOATS) * 4)

__device__ __forceinline__ void grid_barrier(unsigned target)
{
    __threadfence();
    __syncthreads();
    if (threadIdx.x == 0) {
        atomicAdd(&g_bar, 1u);
        while (atomicAdd(&g_bar, 0u) < target) { }
    }
    __syncthreads();
}

__device__ __forceinline__ float sigmoidf_(float v) { return 1.f / (1.f + expf(-v)); }

__global__ void __launch_bounds__(256, 1) lstm_rec_kernel(
    const float* __restrict__ Whh, float* __restrict__ out)
{
    extern __shared__ float smem[];
    float* sw = smem;                    // [32][1024] W rows (gate*8 + warp)
    float* sh = smem + SH_W_FLOATS;      // [2][64 k2][32 b][2]

    const int tid  = threadIdx.x;
    const int bid  = blockIdx.x;
    const int wi   = tid >> 5;
    const int lane = tid & 31;
    const int hc   = (bid << 3) + wi;

    const unsigned sw_base = (unsigned)__cvta_generic_to_shared(smem);
    const unsigned sh_base = sw_base + SH_W_FLOATS * 4u;

    // ---- load this block's 32 W_hh rows into SMEM once ----
    for (int idx = tid; idx < 32 * 256; idx += 256) {
        int r  = idx >> 8;
        int c4 = (idx & 255) << 2;
        int g  = r >> 3, wl = r & 7;
        float4 v = *(const float4*)(Whh + (size_t)(g * Hdim + (bid << 3) + wl) * Hdim + c4);
        *(float4*)(sw + r * 1024 + c4) = v;
    }

    const int hslot = (hc >> 1) * 64 + lane * 2 + (hc & 1);
    g_h2[0][hslot] = 0.f;

    // W row byte bases in shared (per warp)
    const unsigned w0b = sw_base + ((0 * 8 + wi) * 1024) * 4u;
    const unsigned w1b = sw_base + ((1 * 8 + wi) * 1024) * 4u;
    const unsigned w2b = sw_base + ((2 * 8 + wi) * 1024) * 4u;
    const unsigned w3b = sw_base + ((3 * 8 + wi) * 1024) * 4u;

    // preload xw for t=0 (g_xw is complete: gemm kernel finished first)
    const float* xwp = g_xw + (size_t)lane * G4 + hc;
    float x0 = __ldg(xwp + 0);
    float x1 = __ldg(xwp + 1024);
    float x2 = __ldg(xwp + 2048);
    float x3 = __ldg(xwp + 3072);

    float c_state = 0.f;
    unsigned target = NBLK;
    grid_barrier(target);

    for (int t = 0; t < Tlen; t++) {
        const float* hTr = g_h2[t & 1];
        float*       hTw = g_h2[(t + 1) & 1];

        unsigned long long a0 = pack2(x0, 0.f);
        unsigned long long a1 = pack2(x1, 0.f);
        unsigned long long a2 = pack2(x2, 0.f);
        unsigned long long a3 = pack2(x3, 0.f);

        // ---- stage chunk 0 (4096 floats) via L2 ----
        {
            const float* src = hTr + tid * 4;
            float4 r0 = __ldcg((const float4*)(src + 0));
            float4 r1 = __ldcg((const float4*)(src + 1024));
            float4 r2 = __ldcg((const float4*)(src + 2048));
            float4 r3 = __ldcg((const float4*)(src + 3072));
            float* dst = sh + tid * 4;
            *(float4*)(dst + 0)    = r0;
            *(float4*)(dst + 1024) = r1;
            *(float4*)(dst + 2048) = r2;
            *(float4*)(dst + 3072) = r3;
        }
        __syncthreads();

        for (int ch = 0; ch < 8; ch++) {
            const int p = ch & 1;
            float4 n0, n1, n2, n3;
            if (ch < 7) {
                const float* src = hTr + (ch + 1) * 4096 + tid * 4;
                n0 = __ldcg((const float4*)(src + 0));
                n1 = __ldcg((const float4*)(src + 1024));
                n2 = __ldcg((const float4*)(src + 2048));
                n3 = __ldcg((const float4*)(src + 3072));
            }
            const unsigned shp = sh_base + (unsigned)(p * 4096 * 4) + (unsigned)(lane * 8);
            const unsigned wof = (unsigned)(ch * 128 * 4);   // byte offset in W row
#pragma unroll
            for (int k4 = 0; k4 < 32; k4++) {
                unsigned long long h01 = lds_u64(shp + (unsigned)((k4 * 2 + 0) * 256));
                unsigned long long h23 = lds_u64(shp + (unsigned)((k4 * 2 + 1) * 256));
                unsigned long long w01, w23;
                lds_v2u64(w0b + wof + (unsigned)(k4 * 16), w01, w23);
                fma2(a0, w01, h01); fma2(a0, w23, h23);
                lds_v2u64(w1b + wof + (unsigned)(k4 * 16), w01, w23);
                fma2(a1, w01, h01); fma2(a1, w23, h23);
                lds_v2u64(w2b + wof + (unsigned)(k4 * 16), w01, w23);
                fma2(a2, w01, h01); fma2(a2, w23, h23);
                lds_v2u64(w3b + wof + (unsigned)(k4 * 16), w01, w23);
                fma2(a3, w01, h01); fma2(a3, w23, h23);
            }
            if (ch < 7) {
                float* dst = sh + (1 - p) * 4096 + tid * 4;
                *(float4*)(dst + 0)    = n0;
                *(float4*)(dst + 1024) = n1;
                *(float4*)(dst + 2048) = n2;
                *(float4*)(dst + 3072) = n3;
                __syncthreads();
            }
        }

        float lo, hi;
        unpack2(a0, lo, hi); float zi = lo + hi;
        unpack2(a1, lo, hi); float zf = lo + hi;
        unpack2(a2, lo, hi); float zg = lo + hi;
        unpack2(a3, lo, hi); float zo = lo + hi;

        float ig = sigmoidf_(zi);
        float fg = sigmoidf_(zf);
        float gg = tanhf(zg);
        float og = sigmoidf_(zo);
        c_state = fmaf(fg, c_state, ig * gg);
        float hv = og * tanhf(c_state);

        hTw[hslot] = hv;
        out[(size_t)lane * (Tlen * Hdim) + (size_t)t * Hdim + hc] = hv;

        // prefetch next step's input projection before the barrier spin
        if (t + 1 < Tlen) {
            const float* nx = xwp + (size_t)(t + 1) * (Bsz * G4);
            x0 = __ldg(nx + 0);
            x1 = __ldg(nx + 1024);
            x2 = __ldg(nx + 2048);
            x3 = __ldg(nx + 3072);
        }

        target += NBLK;
        grid_barrier(target);
    }
}

// =======================================================================
extern "C" void kernel_launch(void* const* d_in, const int* in_sizes, int n_in,
                              void* d_out, int out_size)
{
    const float* x    = (const float*)d_in[0];
    const float* Wih  = (const float*)d_in[1];
    const float* Whh  = (const float*)d_in[2];
    const float* bias = (const float*)d_in[3];
    float* out = (float*)d_out;

    cudaFuncSetAttribute(lstm_rec_kernel,
                         cudaFuncAttributeMaxDynamicSharedMemorySize, SMEM_BYTES);

    dim3 g1(G4 / BN, (Bsz * Tlen) / BM);   // (64, 256)
    gemm_xw_kernel<<<g1, 256>>>(x, Wih, bias);

    lstm_rec_kernel<<<NBLK, 256, SMEM_BYTES>>>(Whh, out);
}

// round 3
// speedup vs baseline: 1.2438x; 1.1512x over previous
#include <cuda_runtime.h>
#include <math.h>

#define Bsz  32
#define Tlen 512
#define Idim 1024
#define Hdim 1024
#define G4   4096

// ---------------- device scratch ----------------
__device__ float g_xw[(size_t)Tlen * Bsz * G4];   // [t][b][4H]
__device__ float g_h2[2][Hdim * Bsz];             // pair-interleaved: slot=(k>>1)*64+b*2+(k&1)
__device__ unsigned int g_bar;

// ---------------- f32x2 helpers ----------------
__device__ __forceinline__ void fma2(unsigned long long& acc,
                                     unsigned long long a, unsigned long long b)
{
    asm volatile("fma.rn.f32x2 %0, %1, %2, %0;" : "+l"(acc) : "l"(a), "l"(b));
}
__device__ __forceinline__ unsigned long long pack2(float lo, float hi)
{
    unsigned long long r;
    asm("mov.b64 %0, {%1, %2};" : "=l"(r) : "f"(lo), "f"(hi));
    return r;
}
__device__ __forceinline__ unsigned long long bcast2(float v)
{
    unsigned long long r;
    asm("mov.b64 %0, {%1, %1};" : "=l"(r) : "f"(v));
    return r;
}
__device__ __forceinline__ void unpack2(unsigned long long p, float& lo, float& hi)
{
    asm("mov.b64 {%0, %1}, %2;" : "=f"(lo), "=f"(hi) : "l"(p));
}
__device__ __forceinline__ void lds_v2u64(unsigned addr,
                                          unsigned long long& a, unsigned long long& b)
{
    asm volatile("ld.shared.v2.u64 {%0, %1}, [%2];" : "=l"(a), "=l"(b) : "r"(addr));
}
__device__ __forceinline__ unsigned long long lds_u64(unsigned addr)
{
    unsigned long long r;
    asm volatile("ld.shared.b64 %0, [%1];" : "=l"(r) : "r"(addr));
    return r;
}

// =======================================================================
// Phase 1: g_xw[t][b][n] = sum_k x[(b,t)][k]*Wih[n][k] + bias[n]
// 128x128 tile, BK=16, 256 threads, 8x8 microtile, f32x2, double-buffered.
// =======================================================================
#define P1_BK   16
#define P1_PITCH 132   // padded row (floats); 132*4B, 16B-aligned per k row

__global__ void __launch_bounds__(256, 2) gemm_xw_kernel(
    const float* __restrict__ x, const float* __restrict__ Wih,
    const float* __restrict__ bias)
{
    __shared__ float As[2][P1_BK][P1_PITCH];
    __shared__ float Bs[2][P1_BK][P1_PITCH];

    if (blockIdx.x == 0 && blockIdx.y == 0 && threadIdx.x == 0) g_bar = 0u;

    const int tid = threadIdx.x;
    const int bn  = blockIdx.x * 128;
    const int bm  = blockIdx.y * 128;
    const int tx8 = (tid & 15) << 3;     // 0..120 (col within tile)
    const int ty8 = (tid >> 4) << 3;     // 0..120 (row within tile)

    // staging: thread owns (row = tid>>1, kq = (tid&1)*8), 8 consecutive k
    const int srow = tid >> 1;
    const int skq  = (tid & 1) << 3;
    const float* Ag = x   + (size_t)(bm + srow) * Idim + skq;
    const float* Bg = Wih + (size_t)(bn + srow) * Idim + skq;

    const unsigned bsb = (unsigned)__cvta_generic_to_shared(&Bs[0][0][0]);

    float4 ra0 = *(const float4*)(Ag + 0);
    float4 ra1 = *(const float4*)(Ag + 4);
    float4 rb0 = *(const float4*)(Bg + 0);
    float4 rb1 = *(const float4*)(Bg + 4);

    unsigned long long acc[8][4];
#pragma unroll
    for (int i = 0; i < 8; i++)
#pragma unroll
        for (int j = 0; j < 4; j++) acc[i][j] = 0ull;

    // store k0=0 into buf 0
    {
        float va[8] = {ra0.x, ra0.y, ra0.z, ra0.w, ra1.x, ra1.y, ra1.z, ra1.w};
        float vb[8] = {rb0.x, rb0.y, rb0.z, rb0.w, rb1.x, rb1.y, rb1.z, rb1.w};
#pragma unroll
        for (int j = 0; j < 8; j++) {
            As[0][skq + j][srow] = va[j];
            Bs[0][skq + j][srow] = vb[j];
        }
    }
    __syncthreads();

    int p = 0;
    for (int kt = 0; kt < Idim / P1_BK; kt++) {
        if (kt + 1 < Idim / P1_BK) {
            const float* ag = Ag + (kt + 1) * P1_BK;
            const float* bg = Bg + (kt + 1) * P1_BK;
            ra0 = *(const float4*)(ag + 0);
            ra1 = *(const float4*)(ag + 4);
            rb0 = *(const float4*)(bg + 0);
            rb1 = *(const float4*)(bg + 4);
        }

#pragma unroll
        for (int k = 0; k < P1_BK; k++) {
            float4 a0 = *(const float4*)&As[p][k][ty8];
            float4 a1 = *(const float4*)&As[p][k][ty8 + 4];
            unsigned baddr = bsb +
                (unsigned)(((p * P1_BK + k) * P1_PITCH + tx8) * 4);
            unsigned long long b0, b1, b2, b3;
            lds_v2u64(baddr,      b0, b1);
            lds_v2u64(baddr + 16, b2, b3);
            float av[8] = {a0.x, a0.y, a0.z, a0.w, a1.x, a1.y, a1.z, a1.w};
#pragma unroll
            for (int i = 0; i < 8; i++) {
                unsigned long long aa = bcast2(av[i]);
                fma2(acc[i][0], aa, b0);
                fma2(acc[i][1], aa, b1);
                fma2(acc[i][2], aa, b2);
                fma2(acc[i][3], aa, b3);
            }
        }

        if (kt + 1 < Idim / P1_BK) {
            __syncthreads();   // all warps finished reading buf p (hence p^1 too)
            float va[8] = {ra0.x, ra0.y, ra0.z, ra0.w, ra1.x, ra1.y, ra1.z, ra1.w};
            float vb[8] = {rb0.x, rb0.y, rb0.z, rb0.w, rb1.x, rb1.y, rb1.z, rb1.w};
            int q = p ^ 1;
#pragma unroll
            for (int j = 0; j < 8; j++) {
                As[q][skq + j][srow] = va[j];
                Bs[q][skq + j][srow] = vb[j];
            }
            __syncthreads();
            p = q;
        }
    }

    float4 bb0 = *(const float4*)&bias[bn + tx8];
    float4 bb1 = *(const float4*)&bias[bn + tx8 + 4];
#pragma unroll
    for (int i = 0; i < 8; i++) {
        int m = bm + ty8 + i;
        int t = m & (Tlen - 1);
        int b = m >> 9;
        float4 o0, o1;
        unpack2(acc[i][0], o0.x, o0.y);
        unpack2(acc[i][1], o0.z, o0.w);
        unpack2(acc[i][2], o1.x, o1.y);
        unpack2(acc[i][3], o1.z, o1.w);
        o0.x += bb0.x; o0.y += bb0.y; o0.z += bb0.z; o0.w += bb0.w;
        o1.x += bb1.x; o1.y += bb1.y; o1.z += bb1.z; o1.w += bb1.w;
        float* dst = &g_xw[(size_t)t * (Bsz * G4) + (size_t)b * G4 + bn + tx8];
        *(float4*)(dst + 0) = o0;
        *(float4*)(dst + 4) = o1;
    }
}

// =======================================================================
// Phase 2: persistent recurrence. 128 blocks x 128 threads (4 warps).
// Warp wi owns 2 h-columns (hc0=bid*8+wi*2, hc1=hc0+1) x 4 gates;
// lane = batch. c-state (x2) register resident. W_hh slice in SMEM.
// =======================================================================
#define NBLK 128
#define SH_W_FLOATS (32 * 1024)          // 128 KB
#define SH_H_FLOATS (2 * 128 * 32)       // 32 KB double-buffered chunk
#define SMEM_BYTES ((SH_W_FLOATS + SH_H_FLOATS) * 4)

__device__ __forceinline__ void grid_barrier(unsigned target)
{
    __threadfence();
    __syncthreads();
    if (threadIdx.x == 0) {
        atomicAdd(&g_bar, 1u);
        while (atomicAdd(&g_bar, 0u) < target) { }
    }
    __syncthreads();
}

__device__ __forceinline__ float sigmoidf_(float v) { return 1.f / (1.f + expf(-v)); }

__global__ void __launch_bounds__(128, 1) lstm_rec_kernel(
    const float* __restrict__ Whh, float* __restrict__ out)
{
    extern __shared__ float smem[];
    float* sw = smem;                    // [32 rows][1024]; row r = gate*8 + local_hcol
    float* sh = smem + SH_W_FLOATS;      // [2][64 k2][32 b][2]

    const int tid  = threadIdx.x;
    const int bid  = blockIdx.x;
    const int wi   = tid >> 5;           // 0..3
    const int lane = tid & 31;           // batch
    const int hc0  = (bid << 3) + (wi << 1);

    const unsigned sw_base = (unsigned)__cvta_generic_to_shared(smem);
    const unsigned sh_base = sw_base + SH_W_FLOATS * 4u;

    // ---- load 32 W_hh rows (4 gates x 8 local hcols) into SMEM once ----
    for (int idx = tid; idx < 32 * 256; idx += 128) {
        int r  = idx >> 8;
        int c4 = (idx & 255) << 2;
        int g  = r >> 3, wl = r & 7;
        float4 v = *(const float4*)(Whh + (size_t)(g * Hdim + (bid << 3) + wl) * Hdim + c4);
        *(float4*)(sw + r * 1024 + c4) = v;
    }

    // init h buffer 0 (this warp's two columns)
    const int hslot = (hc0 >> 1) * 64 + lane * 2;   // hc0 even
    *(unsigned long long*)&g_h2[0][hslot] = 0ull;

    // W row byte bases for the 8 rows this warp uses: [gate][col]
    unsigned wb[4][2];
#pragma unroll
    for (int g = 0; g < 4; g++)
#pragma unroll
        for (int c = 0; c < 2; c++)
            wb[g][c] = sw_base + (unsigned)(((g * 8 + (wi << 1) + c) * 1024) * 4);

    // preload xw for t=0 : 4 gates x (hc0,hc1)
    const float* xwp = g_xw + (size_t)lane * G4 + hc0;
    float2 xv[4];
#pragma unroll
    for (int g = 0; g < 4; g++) xv[g] = *(const float2*)(xwp + g * 1024);

    float cs0 = 0.f, cs1 = 0.f;
    unsigned target = NBLK;
    grid_barrier(target);

    for (int t = 0; t < Tlen; t++) {
        const float* hTr = g_h2[t & 1];
        float*       hTw = g_h2[(t + 1) & 1];

        unsigned long long a[4][2];
#pragma unroll
        for (int g = 0; g < 4; g++) {
            a[g][0] = pack2(xv[g].x, 0.f);
            a[g][1] = pack2(xv[g].y, 0.f);
        }

        // ---- stage chunk 0 (4096 floats) : 8 float4 per thread ----
        {
            const float* src = hTr + tid * 4;
            float4 r[8];
#pragma unroll
            for (int m = 0; m < 8; m++) r[m] = __ldcg((const float4*)(src + m * 512));
            float* dst = sh + tid * 4;
#pragma unroll
            for (int m = 0; m < 8; m++) *(float4*)(dst + m * 512) = r[m];
        }
        __syncthreads();

        for (int ch = 0; ch < 8; ch++) {
            const int p = ch & 1;
            float4 nr[8];
            if (ch < 7) {
                const float* src = hTr + (ch + 1) * 4096 + tid * 4;
#pragma unroll
                for (int m = 0; m < 8; m++) nr[m] = __ldcg((const float4*)(src + m * 512));
            }
            const unsigned shp = sh_base + (unsigned)(p * 4096 * 4) + (unsigned)(lane * 8);
            const unsigned wof = (unsigned)(ch * 512);   // ch*128 k * 4B
#pragma unroll 8
            for (int k4 = 0; k4 < 32; k4++) {
                unsigned long long h01 = lds_u64(shp + (unsigned)((k4 * 2 + 0) * 256));
                unsigned long long h23 = lds_u64(shp + (unsigned)((k4 * 2 + 1) * 256));
                unsigned long long w01, w23;
#pragma unroll
                for (int g = 0; g < 4; g++) {
                    lds_v2u64(wb[g][0] + wof + (unsigned)(k4 * 16), w01, w23);
                    fma2(a[g][0], w01, h01); fma2(a[g][0], w23, h23);
                    lds_v2u64(wb[g][1] + wof + (unsigned)(k4 * 16), w01, w23);
                    fma2(a[g][1], w01, h01); fma2(a[g][1], w23, h23);
                }
            }
            if (ch < 7) {
                float* dst = sh + (1 - p) * 4096 + tid * 4;
#pragma unroll
                for (int m = 0; m < 8; m++) *(float4*)(dst + m * 512) = nr[m];
                __syncthreads();
            }
        }

        // ---- gates for 2 columns ----
        float lo, hi;
        unpack2(a[0][0], lo, hi); float zi0 = lo + hi;
        unpack2(a[1][0], lo, hi); float zf0 = lo + hi;
        unpack2(a[2][0], lo, hi); float zg0 = lo + hi;
        unpack2(a[3][0], lo, hi); float zo0 = lo + hi;
        unpack2(a[0][1], lo, hi); float zi1 = lo + hi;
        unpack2(a[1][1], lo, hi); float zf1 = lo + hi;
        unpack2(a[2][1], lo, hi); float zg1 = lo + hi;
        unpack2(a[3][1], lo, hi); float zo1 = lo + hi;

        cs0 = fmaf(sigmoidf_(zf0), cs0, sigmoidf_(zi0) * tanhf(zg0));
        cs1 = fmaf(sigmoidf_(zf1), cs1, sigmoidf_(zi1) * tanhf(zg1));
        float hv0 = sigmoidf_(zo0) * tanhf(cs0);
        float hv1 = sigmoidf_(zo1) * tanhf(cs1);

        *(unsigned long long*)&hTw[hslot] = pack2(hv0, hv1);
        float2 ov; ov.x = hv0; ov.y = hv1;
        *(float2*)&out[(size_t)lane * (Tlen * Hdim) + (size_t)t * Hdim + hc0] = ov;

        if (t + 1 < Tlen) {
            const float* nx = xwp + (size_t)(t + 1) * (Bsz * G4);
#pragma unroll
            for (int g = 0; g < 4; g++) xv[g] = *(const float2*)(nx + g * 1024);
        }

        target += NBLK;
        grid_barrier(target);
    }
}

// =======================================================================
extern "C" void kernel_launch(void* const* d_in, const int* in_sizes, int n_in,
                              void* d_out, int out_size)
{
    const float* x    = (const float*)d_in[0];
    const float* Wih  = (const float*)d_in[1];
    const float* Whh  = (const float*)d_in[2];
    const float* bias = (const float*)d_in[3];
    float* out = (float*)d_out;

    cudaFuncSetAttribute(lstm_rec_kernel,
                         cudaFuncAttributeMaxDynamicSharedMemorySize, SMEM_BYTES);

    dim3 g1(G4 / 128, (Bsz * Tlen) / 128);   // (32, 128)
    gemm_xw_kernel<<<g1, 256>>>(x, Wih, bias);

    lstm_rec_kernel<<<NBLK, 128, SMEM_BYTES>>>(Whh, out);
}